// round 2
// baseline (speedup 1.0000x reference)
#include <cuda_runtime.h>

// Problem constants (compile-time)
namespace {
constexpr int B = 512, S = 96, N = 64, H = 512, E = 512;
constexpr int NE = E + N;      // 576 edges incl self-loops
constexpr int NTHREADS = 256;

// shared memory layout (4-byte word offsets)
constexpr int W_SRC  = 0;                 // int[576]
constexpr int W_DST  = W_SRC + NE;        // int[576]
constexpr int W_DEG  = W_DST + NE;        // int[64]
constexpr int W_OFFS = W_DEG + N;         // int[65]
constexpr int W_CNT  = W_OFFS + N + 1;    // int[64]
constexpr int W_EID  = W_CNT + N;         // int[576]
constexpr int W_DINV = W_EID + NE;        // float[64]
constexpr int XT_LD  = 97;                // padded row stride (conflict-free)
constexpr int W_XT   = W_DINV + N;        // float[64][97]  (reused as t2)
constexpr int W_XAGG = W_XT + N * XT_LD;  // float[64][97]
constexpr int W2T_LD = 65;
constexpr int WBUF_WORDS = 96 * 65;       // 6240 (also holds 64*97=6208 W1 tile)
constexpr int W_WBUF = W_XAGG + N * XT_LD;
constexpr int W_BIG  = W_WBUF + WBUF_WORDS;
constexpr int H1_LD  = 513;
constexpr int BIG_WORDS = N * H1_LD;      // 32832 words = 128.2 KB
constexpr int SMEM_WORDS = W_BIG + BIG_WORDS;
constexpr int SMEM_BYTES = SMEM_WORDS * 4; // ~213.9 KB < 227 KB limit

constexpr int H2P_LD = 99;                // padded circular buffer [64][99]
constexpr int CWT_LD = 193;               // conv weight tile [64][193]
}

__global__ __launch_bounds__(NTHREADS, 1)
void gcn_fused_kernel(const float* __restrict__ x,
                      const int*   __restrict__ edge_index,
                      const float* __restrict__ W1,
                      const float* __restrict__ b1,
                      const float* __restrict__ W2,
                      const float* __restrict__ b2,
                      const float* __restrict__ conv_w,
                      float*       __restrict__ out)
{
    extern __shared__ float sm[];
    int*   s_src  = (int*)(sm + W_SRC);
    int*   s_dst  = (int*)(sm + W_DST);
    int*   s_deg  = (int*)(sm + W_DEG);
    int*   s_off  = (int*)(sm + W_OFFS);
    int*   s_cnt  = (int*)(sm + W_CNT);
    int*   s_eid  = (int*)(sm + W_EID);
    float* s_dinv = sm + W_DINV;
    float* s_xT   = sm + W_XT;    // [N][97]; later t2
    float* s_xagg = sm + W_XAGG;  // [N][97]
    float* s_wbuf = sm + W_WBUF;
    float* s_h1   = sm + W_BIG;                 // [N][513]
    float* s_h2p  = sm + W_BIG;                 // [N][99]  (h1 dead by then)
    float* s_cwt  = sm + W_BIG + N * H2P_LD;    // [64][193]

    const int tid = threadIdx.x;
    const int bid = blockIdx.x;
    const int tx  = tid & 15;
    const int ty  = tid >> 4;

    // ---------- Phase 0: load edges + x, build degrees ----------
    const int* ei = edge_index + (size_t)bid * 2 * E;
    for (int i = tid; i < E; i += NTHREADS) {
        s_src[i] = ei[i];
        s_dst[i] = ei[E + i];
    }
    if (tid < N) {
        s_src[E + tid] = tid;   // self loops
        s_dst[E + tid] = tid;
        s_deg[tid] = 0;
        s_cnt[tid] = 0;
    }
    const float* xb = x + (size_t)bid * S * N;
    for (int i = tid; i < S * N; i += NTHREADS) {
        int s = i >> 6, n = i & 63;           // x[b][s][n] -> xT[n][s]
        s_xT[n * XT_LD + s] = xb[i];
    }
    __syncthreads();

    for (int i = tid; i < NE; i += NTHREADS) atomicAdd(&s_deg[s_dst[i]], 1);
    __syncthreads();
    if (tid < N) s_dinv[tid] = rsqrtf((float)s_deg[tid]);
    if (tid == 0) {
        int acc = 0;
        for (int n = 0; n < N; n++) { s_off[n] = acc; acc += s_deg[n]; }
        s_off[N] = acc;
    }
    __syncthreads();
    // CSR scatter: bucket edge ids by dst
    for (int i = tid; i < NE; i += NTHREADS) {
        int d = s_dst[i];
        int pos = s_off[d] + atomicAdd(&s_cnt[d], 1);
        s_eid[pos] = i;
    }
    __syncthreads();

    // ---------- Phase 1: aggregate x:  xagg = A_hat * xT ----------
    for (int p = tid; p < N * S; p += NTHREADS) {
        int n = p & 63, s = p >> 6;
        float acc = 0.f;
        const int e0 = s_off[n], e1 = s_off[n + 1];
        for (int q = e0; q < e1; q++) {
            int sr = s_src[s_eid[q]];
            acc += s_dinv[sr] * s_xT[sr * XT_LD + s];
        }
        s_xagg[n * XT_LD + s] = acc * s_dinv[n];
    }
    __syncthreads();

    // ---------- Phase 2: GEMM1 + b1 + relu:  h1[n][h] = relu(xagg @ W1^T + b1) ----------
    for (int ht = 0; ht < H; ht += 64) {
        for (int i = tid; i < 64 * S; i += NTHREADS) {
            int hh = i / S, s = i - hh * S;
            s_wbuf[hh * XT_LD + s] = W1[(size_t)(ht + hh) * S + s];
        }
        __syncthreads();
        float acc[4][4];
        #pragma unroll
        for (int i = 0; i < 4; i++)
            #pragma unroll
            for (int j = 0; j < 4; j++) acc[i][j] = 0.f;
        #pragma unroll 4
        for (int s = 0; s < S; s++) {
            float a[4], w[4];
            #pragma unroll
            for (int i = 0; i < 4; i++) a[i] = s_xagg[(ty + 16 * i) * XT_LD + s];
            #pragma unroll
            for (int j = 0; j < 4; j++) w[j] = s_wbuf[(tx + 16 * j) * XT_LD + s];
            #pragma unroll
            for (int i = 0; i < 4; i++)
                #pragma unroll
                for (int j = 0; j < 4; j++) acc[i][j] = fmaf(a[i], w[j], acc[i][j]);
        }
        #pragma unroll
        for (int j = 0; j < 4; j++) {
            float bv = b1[ht + tx + 16 * j];
            #pragma unroll
            for (int i = 0; i < 4; i++)
                s_h1[(ty + 16 * i) * H1_LD + ht + tx + 16 * j] =
                    fmaxf(acc[i][j] + bv, 0.f);
        }
        __syncthreads();
    }

    // ---------- Phase 3: GEMM2: t2[n][s] = h1 @ W2^T  (into s_xT) ----------
    {
        float acc[4][6];
        #pragma unroll
        for (int i = 0; i < 4; i++)
            #pragma unroll
            for (int j = 0; j < 6; j++) acc[i][j] = 0.f;
        for (int kt = 0; kt < H; kt += 64) {
            for (int i = tid; i < S * 64; i += NTHREADS) {
                int s = i >> 6, kk = i & 63;
                s_wbuf[s * W2T_LD + kk] = W2[(size_t)s * H + kt + kk];
            }
            __syncthreads();
            #pragma unroll 4
            for (int kk = 0; kk < 64; kk++) {
                float a[4], w[6];
                #pragma unroll
                for (int i = 0; i < 4; i++) a[i] = s_h1[(ty + 16 * i) * H1_LD + kt + kk];
                #pragma unroll
                for (int j = 0; j < 6; j++) w[j] = s_wbuf[(tx + 16 * j) * W2T_LD + kk];
                #pragma unroll
                for (int i = 0; i < 4; i++)
                    #pragma unroll
                    for (int j = 0; j < 6; j++) acc[i][j] = fmaf(a[i], w[j], acc[i][j]);
            }
            __syncthreads();
        }
        #pragma unroll
        for (int i = 0; i < 4; i++)
            #pragma unroll
            for (int j = 0; j < 6; j++)
                s_xT[(ty + 16 * i) * XT_LD + tx + 16 * j] = acc[i][j];
    }
    __syncthreads();

    // ---------- Phase 4: aggregate t2 (+b2) -> h2p with circular padding ----------
    // h2p[n][0] = h2[n][95]; h2p[n][t+1] = h2[n][t]; h2p[n][97] = h2[n][0]
    for (int p = tid; p < N * S; p += NTHREADS) {
        int n = p & 63, s = p >> 6;
        float acc = 0.f;
        const int e0 = s_off[n], e1 = s_off[n + 1];
        for (int q = e0; q < e1; q++) {
            int sr = s_src[s_eid[q]];
            acc += s_dinv[sr] * s_xT[sr * XT_LD + s];
        }
        float v = acc * s_dinv[n] + b2[s];
        s_h2p[n * H2P_LD + s + 1] = v;
        if (s == 0)     s_h2p[n * H2P_LD + S + 1] = v;
        if (s == S - 1) s_h2p[n * H2P_LD + 0] = v;
    }
    __syncthreads();

    // ---------- Phase 5: Conv1d(k=3, circular) + transpose -> out[b][s][o] ----------
    float* outb = out + (size_t)bid * S * H;
    for (int ot = 0; ot < H; ot += 64) {
        for (int i = tid; i < 64 * 192; i += NTHREADS) {
            int oo = i / 192, j = i - oo * 192;
            s_cwt[oo * CWT_LD + j] = conv_w[(size_t)(ot + oo) * 192 + j];
        }
        __syncthreads();
        float acc[4][6];
        #pragma unroll
        for (int jj = 0; jj < 4; jj++)
            #pragma unroll
            for (int j = 0; j < 6; j++) acc[jj][j] = 0.f;
        for (int ic = 0; ic < N; ic++) {
            float w[4][3];
            #pragma unroll
            for (int jj = 0; jj < 4; jj++)
                #pragma unroll
                for (int k = 0; k < 3; k++)
                    w[jj][k] = s_cwt[(tx + 16 * jj) * CWT_LD + ic * 3 + k];
            #pragma unroll
            for (int j = 0; j < 6; j++) {
                float h0 = s_h2p[ic * H2P_LD + ty + 16 * j];
                float h1v = s_h2p[ic * H2P_LD + ty + 16 * j + 1];
                float h2v = s_h2p[ic * H2P_LD + ty + 16 * j + 2];
                #pragma unroll
                for (int jj = 0; jj < 4; jj++)
                    acc[jj][j] = fmaf(w[jj][0], h0,
                                 fmaf(w[jj][1], h1v,
                                 fmaf(w[jj][2], h2v, acc[jj][j])));
            }
        }
        #pragma unroll
        for (int j = 0; j < 6; j++)
            #pragma unroll
            for (int jj = 0; jj < 4; jj++)
                outb[(size_t)(ty + 16 * j) * H + ot + tx + 16 * jj] = acc[jj][j];
        __syncthreads();
    }
}

extern "C" void kernel_launch(void* const* d_in, const int* in_sizes, int n_in,
                              void* d_out, int out_size)
{
    const float* x   = (const float*)d_in[0];
    const int*   ei  = (const int*)  d_in[1];
    const float* W1  = (const float*)d_in[2];
    const float* b1  = (const float*)d_in[3];
    const float* W2  = (const float*)d_in[4];
    const float* b2  = (const float*)d_in[5];
    const float* cw  = (const float*)d_in[6];
    float* out = (float*)d_out;

    cudaFuncSetAttribute(gcn_fused_kernel,
                         cudaFuncAttributeMaxDynamicSharedMemorySize, SMEM_BYTES);
    gcn_fused_kernel<<<B, NTHREADS, SMEM_BYTES>>>(x, ei, W1, b1, W2, b2, cw, out);
}

// round 4
// speedup vs baseline: 1.2773x; 1.2773x over previous
#include <cuda_runtime.h>

namespace {
constexpr int B = 512, S = 96, N = 64, H = 512, E = 512;
constexpr int NE = E + N;      // 576 edges incl self-loops
constexpr int NTHREADS = 256;

// ---- shared memory layout (word offsets) ----
constexpr int W_SRC  = 0;                 // int[576]
constexpr int W_DST  = W_SRC + NE;        // int[576]
constexpr int W_DEG  = W_DST + NE;        // int[64]
constexpr int W_OFFS = W_DEG + N;         // int[65]
constexpr int W_CNT  = W_OFFS + N + 1;    // int[64]
constexpr int W_EID  = W_CNT + N;         // int[576]
constexpr int W_DINV = W_EID + NE;        // float[64]
constexpr int META_END = W_DINV + N;      // 1985

constexpr int XT_LD  = 97;
constexpr int W_XT   = META_END;                 // float[64][97] (x^T, later t2)
constexpr int U0     = W_XT + N * XT_LD;         // start of union region

// --- phases 1-3 view of union region ---
constexpr int W_XAGG = U0;                       // float[64][97]
constexpr int W2T_LD = 65;
constexpr int WBUF_WORDS = 96 * 65;              // 6240 >= 64*97=6208
constexpr int W_WBUF = W_XAGG + N * XT_LD;       // weight tile (W1 or W2)
constexpr int H1T_LD = 65;
constexpr int W_H1T  = W_WBUF + WBUF_WORDS;      // float[64][65] h1 tile

// --- phases 4-5 view of union region ---
constexpr int H2P_LD = 99;
constexpr int W_H2P  = U0;                       // float[64][99]
constexpr int CWT_LD = 193;
constexpr int W_CWT  = W_H2P + N * H2P_LD;       // float[64][193]

constexpr int UNION_A = (W_H1T + N * H1T_LD) - U0;   // 16608
constexpr int UNION_B = (W_CWT + N * CWT_LD) - U0;   // 18688
constexpr int UNION_WORDS = (UNION_A > UNION_B) ? UNION_A : UNION_B;
constexpr int SMEM_WORDS = U0 + UNION_WORDS;     // 26881
constexpr int SMEM_BYTES = SMEM_WORDS * 4;       // ~107.5 KB -> 2 CTAs/SM
}

__global__ __launch_bounds__(NTHREADS, 2)
void gcn_fused_kernel(const float* __restrict__ x,
                      const int*   __restrict__ edge_index,
                      const float* __restrict__ W1,
                      const float* __restrict__ b1,
                      const float* __restrict__ W2,
                      const float* __restrict__ b2,
                      const float* __restrict__ conv_w,
                      float*       __restrict__ out)
{
    extern __shared__ float sm[];
    int*   s_src  = (int*)(sm + W_SRC);
    int*   s_dst  = (int*)(sm + W_DST);
    int*   s_deg  = (int*)(sm + W_DEG);
    int*   s_off  = (int*)(sm + W_OFFS);
    int*   s_cnt  = (int*)(sm + W_CNT);
    int*   s_eid  = (int*)(sm + W_EID);
    float* s_dinv = sm + W_DINV;
    float* s_xT   = sm + W_XT;    // [N][97]; later holds t2
    float* s_xagg = sm + W_XAGG;  // [N][97]
    float* s_wbuf = sm + W_WBUF;  // W1 tile [64][97] or W2 tile [96][65]
    float* s_h1t  = sm + W_H1T;   // [64][65] current h1 tile
    float* s_h2p  = sm + W_H2P;   // [64][99]
    float* s_cwt  = sm + W_CWT;   // [64][193]

    const int tid = threadIdx.x;
    const int bid = blockIdx.x;
    const int tx  = tid & 15;
    const int ty  = tid >> 4;

    // ---------- Phase 0: load edges + x, build degrees / CSR ----------
    const int* ei = edge_index + (size_t)bid * 2 * E;
    for (int i = tid; i < E; i += NTHREADS) {
        s_src[i] = ei[i];
        s_dst[i] = ei[E + i];
    }
    if (tid < N) {
        s_src[E + tid] = tid;
        s_dst[E + tid] = tid;
        s_deg[tid] = 0;
        s_cnt[tid] = 0;
    }
    const float* xb = x + (size_t)bid * S * N;
    for (int i = tid; i < S * N; i += NTHREADS) {
        int s = i >> 6, n = i & 63;
        s_xT[n * XT_LD + s] = xb[i];
    }
    __syncthreads();

    for (int i = tid; i < NE; i += NTHREADS) atomicAdd(&s_deg[s_dst[i]], 1);
    __syncthreads();
    if (tid < N) s_dinv[tid] = rsqrtf((float)s_deg[tid]);
    if (tid == 0) {
        int acc = 0;
        for (int n = 0; n < N; n++) { s_off[n] = acc; acc += s_deg[n]; }
        s_off[N] = acc;
    }
    __syncthreads();
    for (int i = tid; i < NE; i += NTHREADS) {
        int d = s_dst[i];
        int pos = s_off[d] + atomicAdd(&s_cnt[d], 1);
        s_eid[pos] = i;
    }
    __syncthreads();

    // ---------- Phase 1: xagg = A_hat * xT ----------
    for (int p = tid; p < N * S; p += NTHREADS) {
        int n = p & 63, s = p >> 6;
        float acc = 0.f;
        const int e0 = s_off[n], e1 = s_off[n + 1];
        for (int q = e0; q < e1; q++) {
            int sr = s_src[s_eid[q]];
            acc += s_dinv[sr] * s_xT[sr * XT_LD + s];
        }
        s_xagg[n * XT_LD + s] = acc * s_dinv[n];
    }
    __syncthreads();

    // ---------- Phase 2+3 fused: per 64-wide H tile, h1 tile -> accumulate t2 ----------
    float acc2[4][6];
    #pragma unroll
    for (int i = 0; i < 4; i++)
        #pragma unroll
        for (int j = 0; j < 6; j++) acc2[i][j] = 0.f;

    for (int kt = 0; kt < H; kt += 64) {
        // load W1 tile [64][S]
        for (int i = tid; i < 64 * S; i += NTHREADS) {
            int hh = i / S, s = i - hh * S;
            s_wbuf[hh * XT_LD + s] = W1[(size_t)(kt + hh) * S + s];
        }
        __syncthreads();

        // h1 tile: rows = nodes (ty + 16i), cols = h (tx + 16j)
        float acc1[4][4];
        #pragma unroll
        for (int i = 0; i < 4; i++)
            #pragma unroll
            for (int j = 0; j < 4; j++) acc1[i][j] = 0.f;
        #pragma unroll 4
        for (int s = 0; s < S; s++) {
            float a[4], w[4];
            #pragma unroll
            for (int i = 0; i < 4; i++) a[i] = s_xagg[(ty + 16 * i) * XT_LD + s];
            #pragma unroll
            for (int j = 0; j < 4; j++) w[j] = s_wbuf[(tx + 16 * j) * XT_LD + s];
            #pragma unroll
            for (int i = 0; i < 4; i++)
                #pragma unroll
                for (int j = 0; j < 4; j++) acc1[i][j] = fmaf(a[i], w[j], acc1[i][j]);
        }
        #pragma unroll
        for (int j = 0; j < 4; j++) {
            float bv = b1[kt + tx + 16 * j];
            #pragma unroll
            for (int i = 0; i < 4; i++)
                s_h1t[(ty + 16 * i) * H1T_LD + tx + 16 * j] =
                    fmaxf(acc1[i][j] + bv, 0.f);
        }
        __syncthreads();

        // load W2 tile [S][64] into same buffer
        for (int i = tid; i < S * 64; i += NTHREADS) {
            int s = i >> 6, kk = i & 63;
            s_wbuf[s * W2T_LD + kk] = W2[(size_t)s * H + kt + kk];
        }
        __syncthreads();

        // accumulate t2 += h1_tile @ W2_tile^T
        #pragma unroll 4
        for (int kk = 0; kk < 64; kk++) {
            float a[4], w[6];
            #pragma unroll
            for (int i = 0; i < 4; i++) a[i] = s_h1t[(ty + 16 * i) * H1T_LD + kk];
            #pragma unroll
            for (int j = 0; j < 6; j++) w[j] = s_wbuf[(tx + 16 * j) * W2T_LD + kk];
            #pragma unroll
            for (int i = 0; i < 4; i++)
                #pragma unroll
                for (int j = 0; j < 6; j++) acc2[i][j] = fmaf(a[i], w[j], acc2[i][j]);
        }
        __syncthreads();
    }
    // write t2 into s_xT (original x is dead)
    #pragma unroll
    for (int i = 0; i < 4; i++)
        #pragma unroll
        for (int j = 0; j < 6; j++)
            s_xT[(ty + 16 * i) * XT_LD + tx + 16 * j] = acc2[i][j];
    __syncthreads();

    // ---------- Phase 4: aggregate t2 (+b2) -> h2p with circular padding ----------
    for (int p = tid; p < N * S; p += NTHREADS) {
        int n = p & 63, s = p >> 6;
        float acc = 0.f;
        const int e0 = s_off[n], e1 = s_off[n + 1];
        for (int q = e0; q < e1; q++) {
            int sr = s_src[s_eid[q]];
            acc += s_dinv[sr] * s_xT[sr * XT_LD + s];
        }
        float v = acc * s_dinv[n] + b2[s];
        s_h2p[n * H2P_LD + s + 1] = v;
        if (s == 0)     s_h2p[n * H2P_LD + S + 1] = v;
        if (s == S - 1) s_h2p[n * H2P_LD + 0] = v;
    }
    __syncthreads();

    // ---------- Phase 5: Conv1d(k=3, circular) + transpose -> out[b][s][o] ----------
    float* outb = out + (size_t)bid * S * H;
    for (int ot = 0; ot < H; ot += 64) {
        for (int i = tid; i < 64 * 192; i += NTHREADS) {
            int oo = i / 192, j = i - oo * 192;
            s_cwt[oo * CWT_LD + j] = conv_w[(size_t)(ot + oo) * 192 + j];
        }
        __syncthreads();
        float acc[4][6];
        #pragma unroll
        for (int jj = 0; jj < 4; jj++)
            #pragma unroll
            for (int j = 0; j < 6; j++) acc[jj][j] = 0.f;
        for (int ic = 0; ic < N; ic++) {
            float w[4][3];
            #pragma unroll
            for (int jj = 0; jj < 4; jj++)
                #pragma unroll
                for (int k = 0; k < 3; k++)
                    w[jj][k] = s_cwt[(tx + 16 * jj) * CWT_LD + ic * 3 + k];
            #pragma unroll
            for (int j = 0; j < 6; j++) {
                float h0  = s_h2p[ic * H2P_LD + ty + 16 * j];
                float h1v = s_h2p[ic * H2P_LD + ty + 16 * j + 1];
                float h2v = s_h2p[ic * H2P_LD + ty + 16 * j + 2];
                #pragma unroll
                for (int jj = 0; jj < 4; jj++)
                    acc[jj][j] = fmaf(w[jj][0], h0,
                                 fmaf(w[jj][1], h1v,
                                 fmaf(w[jj][2], h2v, acc[jj][j])));
            }
        }
        #pragma unroll
        for (int j = 0; j < 6; j++)
            #pragma unroll
            for (int jj = 0; jj < 4; jj++)
                outb[(size_t)(ty + 16 * j) * H + ot + tx + 16 * jj] = acc[jj][j];
        __syncthreads();
    }
}

extern "C" void kernel_launch(void* const* d_in, const int* in_sizes, int n_in,
                              void* d_out, int out_size)
{
    const float* x   = (const float*)d_in[0];
    const int*   ei  = (const int*)  d_in[1];
    const float* W1  = (const float*)d_in[2];
    const float* b1  = (const float*)d_in[3];
    const float* W2  = (const float*)d_in[4];
    const float* b2  = (const float*)d_in[5];
    const float* cw  = (const float*)d_in[6];
    float* out = (float*)d_out;

    cudaFuncSetAttribute(gcn_fused_kernel,
                         cudaFuncAttributeMaxDynamicSharedMemorySize, SMEM_BYTES);
    gcn_fused_kernel<<<B, NTHREADS, SMEM_BYTES>>>(x, ei, W1, b1, W2, b2, cw, out);
}

// round 6
// speedup vs baseline: 1.5220x; 1.1915x over previous
#include <cuda_runtime.h>

namespace {
constexpr int B = 512, S = 96, N = 64, H = 512, E = 512;
constexpr int NE = E + N;
constexpr int NTHREADS = 256;

// ---- shared memory layout (word offsets) ----
constexpr int W_SRC  = 0;                 // int[576]
constexpr int W_DST  = W_SRC + NE;        // int[576]
constexpr int W_DEG  = W_DST + NE;        // int[64]
constexpr int W_OFFS = W_DEG + N;         // int[65]
constexpr int W_CNT  = W_OFFS + N + 1;    // int[64]
constexpr int W_EID  = W_CNT + N;         // int[576]
constexpr int W_DINV = W_EID + NE;        // float[64]
constexpr int META_RAW = W_DINV + N;      // 1985
constexpr int META_END = (META_RAW + 3) & ~3;     // 1988: 16B-aligned

constexpr int XT_LD  = 98;                        // even -> 8B-aligned rows
constexpr int W_XT   = META_END;                  // float[64][98] (x^T, later t2)
constexpr int U0     = W_XT + N * XT_LD;          // 8260, mult of 4

// --- phases 1-3 view ---
constexpr int W_XAGG  = U0;                       // float[64][98]
constexpr int W1T_LD  = 68;                       // mult of 4 -> 16B rows
constexpr int W2T_LD  = 100;                      // even -> 8B rows
constexpr int WBUF_WORDS = 96 * W1T_LD;           // 6528 >= 64*100=6400
constexpr int W_WBUF  = W_XAGG + N * XT_LD;       // 14532, mult of 4
constexpr int H1T_LD  = 68;
constexpr int W_H1T   = W_WBUF + WBUF_WORDS;      // 21060, mult of 4
constexpr int UNION_A = (W_H1T + N * H1T_LD) - U0;

// --- phases 4-5 view ---
constexpr int H2P_LD  = 100;
constexpr int W_H2P   = U0;                       // float[64][100]
constexpr int CWT_LD  = 68;                       // mult of 4
constexpr int W_CWT   = W_H2P + N * H2P_LD;       // 14660, mult of 4
constexpr int UNION_B = (W_CWT + 192 * CWT_LD) - U0;

constexpr int UNION_WORDS = (UNION_A > UNION_B) ? UNION_A : UNION_B;
constexpr int SMEM_WORDS = U0 + UNION_WORDS;
constexpr int SMEM_BYTES = SMEM_WORDS * 4;        // ~108.3 KB -> 2 CTAs/SM

static_assert((W_XT   % 2) == 0, "xT 8B align");
static_assert((W_WBUF % 4) == 0, "wbuf 16B align");
static_assert((W_H1T  % 4) == 0, "h1t align");
static_assert((W_CWT  % 4) == 0, "cwt 16B align");
}

// ---- packed f32x2 helpers ----
__device__ __forceinline__ unsigned long long dup2(float v) {
    unsigned long long r;
    asm("mov.b64 %0, {%1, %1};" : "=l"(r) : "f"(v));
    return r;
}
__device__ __forceinline__ void unpack2(unsigned long long v, float& lo, float& hi) {
    asm("mov.b64 {%0, %1}, %2;" : "=f"(lo), "=f"(hi) : "l"(v));
}
__device__ __forceinline__ void fma2(unsigned long long& d,
                                     unsigned long long a, unsigned long long b) {
    asm("fma.rn.f32x2 %0, %1, %2, %0;" : "+l"(d) : "l"(a), "l"(b));
}

__global__ __launch_bounds__(NTHREADS, 2)
void gcn_fused_kernel(const float* __restrict__ x,
                      const int*   __restrict__ edge_index,
                      const float* __restrict__ W1,
                      const float* __restrict__ b1,
                      const float* __restrict__ W2,
                      const float* __restrict__ b2,
                      const float* __restrict__ conv_w,
                      float*       __restrict__ out)
{
    extern __shared__ float sm[];
    int*   s_src  = (int*)(sm + W_SRC);
    int*   s_dst  = (int*)(sm + W_DST);
    int*   s_deg  = (int*)(sm + W_DEG);
    int*   s_off  = (int*)(sm + W_OFFS);
    int*   s_cnt  = (int*)(sm + W_CNT);
    int*   s_eid  = (int*)(sm + W_EID);
    float* s_dinv = sm + W_DINV;
    float* s_xT   = sm + W_XT;    // [64][98]; later t2
    float* s_xagg = sm + W_XAGG;  // [64][98]
    float* s_wbuf = sm + W_WBUF;  // w1t[96][68] or w2t[64][100]
    float* s_h1t  = sm + W_H1T;   // [64][68]
    float* s_h2p  = sm + W_H2P;   // [64][100]
    float* s_cwt  = sm + W_CWT;   // cwt_t[192][68]

    const int tid = threadIdx.x;
    const int bid = blockIdx.x;
    const int tx  = tid & 15;
    const int ty  = tid >> 4;

    // ---------- Phase 0: edges, x^T, degrees, CSR ----------
    const int* ei = edge_index + (size_t)bid * 2 * E;
    for (int i = tid; i < E; i += NTHREADS) {
        s_src[i] = ei[i];
        s_dst[i] = ei[E + i];
    }
    if (tid < N) {
        s_src[E + tid] = tid;
        s_dst[E + tid] = tid;
        s_deg[tid] = 0;
        s_cnt[tid] = 0;
    }
    const float* xb = x + (size_t)bid * S * N;
    for (int i = tid; i < S * N; i += NTHREADS) {
        int s = i >> 6, n = i & 63;
        s_xT[n * XT_LD + s] = xb[i];
    }
    __syncthreads();

    for (int i = tid; i < NE; i += NTHREADS) atomicAdd(&s_deg[s_dst[i]], 1);
    __syncthreads();
    if (tid < N) s_dinv[tid] = rsqrtf((float)s_deg[tid]);
    if (tid == 0) {
        int acc = 0;
        for (int n = 0; n < N; n++) { s_off[n] = acc; acc += s_deg[n]; }
        s_off[N] = acc;
    }
    __syncthreads();
    for (int i = tid; i < NE; i += NTHREADS) {
        int d = s_dst[i];
        int pos = s_off[d] + atomicAdd(&s_cnt[d], 1);
        s_eid[pos] = i;
    }
    __syncthreads();

    // ---------- Phase 1: xagg = A_hat * x^T ----------
    for (int p = tid; p < N * S; p += NTHREADS) {
        int n = p & 63, s = p >> 6;
        float acc = 0.f;
        const int e0 = s_off[n], e1 = s_off[n + 1];
        for (int q = e0; q < e1; q++) {
            int sr = s_src[s_eid[q]];
            acc += s_dinv[sr] * s_xT[sr * XT_LD + s];
        }
        s_xagg[n * XT_LD + s] = acc * s_dinv[n];
    }
    __syncthreads();

    // ---------- Phase 2+3 fused (f32x2): per 64-wide H tile ----------
    // GEMM2 accumulator: rows n = ty+16i, col-pairs over s = tx*6 + 2jp + {0,1}
    unsigned long long acc2[4][3];
    #pragma unroll
    for (int i = 0; i < 4; i++)
        #pragma unroll
        for (int j = 0; j < 3; j++) acc2[i][j] = 0ull;

    for (int kt = 0; kt < H; kt += 64) {
        // W1 tile transposed: w1t[s][hh] = W1[kt+hh][s]
        for (int i = tid; i < 64 * S; i += NTHREADS) {
            int hh = i / S, s = i - hh * S;
            s_wbuf[s * W1T_LD + hh] = W1[(size_t)(kt + hh) * S + s];
        }
        __syncthreads();

        // GEMM1 tile: rows n = ty+16i, col-pairs h = tx*4 + 2jp + {0,1}
        unsigned long long acc1[4][2];
        #pragma unroll
        for (int i = 0; i < 4; i++) { acc1[i][0] = 0ull; acc1[i][1] = 0ull; }

        #pragma unroll 4
        for (int s = 0; s < S; s++) {
            unsigned long long ad[4];
            #pragma unroll
            for (int i = 0; i < 4; i++)
                ad[i] = dup2(s_xagg[(ty + 16 * i) * XT_LD + s]);
            const ulonglong2 wv =
                *reinterpret_cast<const ulonglong2*>(&s_wbuf[s * W1T_LD + tx * 4]);
            #pragma unroll
            for (int i = 0; i < 4; i++) {
                fma2(acc1[i][0], ad[i], wv.x);
                fma2(acc1[i][1], ad[i], wv.y);
            }
        }
        // bias + relu -> h1t
        #pragma unroll
        for (int jp = 0; jp < 2; jp++) {
            int hc = kt + tx * 4 + 2 * jp;
            float bv0 = b1[hc], bv1 = b1[hc + 1];
            #pragma unroll
            for (int i = 0; i < 4; i++) {
                float v0, v1;
                unpack2(acc1[i][jp], v0, v1);
                v0 = fmaxf(v0 + bv0, 0.f);
                v1 = fmaxf(v1 + bv1, 0.f);
                s_h1t[(ty + 16 * i) * H1T_LD + tx * 4 + 2 * jp]     = v0;
                s_h1t[(ty + 16 * i) * H1T_LD + tx * 4 + 2 * jp + 1] = v1;
            }
        }
        __syncthreads();

        // W2 tile transposed: w2t[kk][s] = W2[s][kt+kk]
        for (int i = tid; i < S * 64; i += NTHREADS) {
            int s = i >> 6, kk = i & 63;
            s_wbuf[kk * W2T_LD + s] = W2[(size_t)s * H + kt + kk];
        }
        __syncthreads();

        // t2 += h1_tile @ W2_tile^T
        #pragma unroll 4
        for (int kk = 0; kk < 64; kk++) {
            unsigned long long ad[4];
            #pragma unroll
            for (int i = 0; i < 4; i++)
                ad[i] = dup2(s_h1t[(ty + 16 * i) * H1T_LD + kk]);
            unsigned long long w0 =
                *reinterpret_cast<const unsigned long long*>(&s_wbuf[kk * W2T_LD + tx * 6]);
            unsigned long long w1 =
                *reinterpret_cast<const unsigned long long*>(&s_wbuf[kk * W2T_LD + tx * 6 + 2]);
            unsigned long long w2 =
                *reinterpret_cast<const unsigned long long*>(&s_wbuf[kk * W2T_LD + tx * 6 + 4]);
            #pragma unroll
            for (int i = 0; i < 4; i++) {
                fma2(acc2[i][0], ad[i], w0);
                fma2(acc2[i][1], ad[i], w1);
                fma2(acc2[i][2], ad[i], w2);
            }
        }
        __syncthreads();
    }
    // store t2 into s_xT
    #pragma unroll
    for (int i = 0; i < 4; i++)
        #pragma unroll
        for (int jp = 0; jp < 3; jp++)
            *reinterpret_cast<unsigned long long*>(
                &s_xT[(ty + 16 * i) * XT_LD + tx * 6 + 2 * jp]) = acc2[i][jp];
    __syncthreads();

    // ---------- Phase 4: aggregate t2 (+b2) -> h2p (circular padded) ----------
    for (int p = tid; p < N * S; p += NTHREADS) {
        int n = p & 63, s = p >> 6;
        float acc = 0.f;
        const int e0 = s_off[n], e1 = s_off[n + 1];
        for (int q = e0; q < e1; q++) {
            int sr = s_src[s_eid[q]];
            acc += s_dinv[sr] * s_xT[sr * XT_LD + s];
        }
        float v = acc * s_dinv[n] + b2[s];
        s_h2p[n * H2P_LD + s + 1] = v;
        if (s == 0)     s_h2p[n * H2P_LD + S + 1] = v;
        if (s == S - 1) s_h2p[n * H2P_LD + 0] = v;
    }
    __syncthreads();

    // ---------- Phase 5: Conv1d(k=3, circular) + transpose (f32x2) ----------
    // output mapping: s = ty*6 + j (j 0..5), o-pairs = ot + tx*4 + 2jp + {0,1}
    float* outb = out + (size_t)bid * S * H;
    for (int ot = 0; ot < H; ot += 64) {
        // conv weights transposed: cwt_t[j][oo] = conv_w[ot+oo][j]
        for (int i = tid; i < 64 * 192; i += NTHREADS) {
            int oo = i / 192, j = i - oo * 192;
            s_cwt[j * CWT_LD + oo] = conv_w[(size_t)(ot + oo) * 192 + j];
        }
        __syncthreads();

        unsigned long long acc[2][6];
        #pragma unroll
        for (int jp = 0; jp < 2; jp++)
            #pragma unroll
            for (int j = 0; j < 6; j++) acc[jp][j] = 0ull;

        for (int ic = 0; ic < N; ic++) {
            // 8 broadcast taps (padded positions ty*6 .. ty*6+7)
            unsigned long long hd[8];
            #pragma unroll
            for (int p = 0; p < 8; p++)
                hd[p] = dup2(s_h2p[ic * H2P_LD + ty * 6 + p]);
            // 3 tap-weight pair vectors
            ulonglong2 w0 = *reinterpret_cast<const ulonglong2*>(
                &s_cwt[(ic * 3 + 0) * CWT_LD + tx * 4]);
            ulonglong2 w1 = *reinterpret_cast<const ulonglong2*>(
                &s_cwt[(ic * 3 + 1) * CWT_LD + tx * 4]);
            ulonglong2 w2 = *reinterpret_cast<const ulonglong2*>(
                &s_cwt[(ic * 3 + 2) * CWT_LD + tx * 4]);
            #pragma unroll
            for (int j = 0; j < 6; j++) {
                fma2(acc[0][j], w0.x, hd[j]);
                fma2(acc[1][j], w0.y, hd[j]);
                fma2(acc[0][j], w1.x, hd[j + 1]);
                fma2(acc[1][j], w1.y, hd[j + 1]);
                fma2(acc[0][j], w2.x, hd[j + 2]);
                fma2(acc[1][j], w2.y, hd[j + 2]);
            }
        }
        #pragma unroll
        for (int j = 0; j < 6; j++) {
            int s = ty * 6 + j;
            #pragma unroll
            for (int jp = 0; jp < 2; jp++)
                *reinterpret_cast<unsigned long long*>(
                    &outb[(size_t)s * H + ot + tx * 4 + 2 * jp]) = acc[jp][j];
        }
        __syncthreads();
    }
}

extern "C" void kernel_launch(void* const* d_in, const int* in_sizes, int n_in,
                              void* d_out, int out_size)
{
    const float* x   = (const float*)d_in[0];
    const int*   ei  = (const int*)  d_in[1];
    const float* W1  = (const float*)d_in[2];
    const float* b1  = (const float*)d_in[3];
    const float* W2  = (const float*)d_in[4];
    const float* b2  = (const float*)d_in[5];
    const float* cw  = (const float*)d_in[6];
    float* out = (float*)d_out;

    cudaFuncSetAttribute(gcn_fused_kernel,
                         cudaFuncAttributeMaxDynamicSharedMemorySize, SMEM_BYTES);
    gcn_fused_kernel<<<B, NTHREADS, SMEM_BYTES>>>(x, ei, W1, b1, W2, b2, cw, out);
}

// round 12
// speedup vs baseline: 1.8640x; 1.2247x over previous
#include <cuda_runtime.h>
#include <cuda_bf16.h>

namespace {
constexpr int B = 512, S = 96, N = 64, H = 512, E = 512;
constexpr int NE = E + N;
constexpr int NTHREADS = 256;
constexpr int KC = 192;                   // conv im2col K

// ---- kernel1 shared memory layout (word offsets) ----
constexpr int W_SRC  = 0;                 // int[576]
constexpr int W_DST  = W_SRC + NE;        // int[576]
constexpr int W_DEG  = W_DST + NE;        // int[64]
constexpr int W_OFFS = W_DEG + N;         // int[65]
constexpr int W_CNT  = W_OFFS + N + 1;    // int[64]
constexpr int W_EID  = W_CNT + N;         // int[576]
constexpr int W_DINV = W_EID + NE;        // float[64]
constexpr int META_RAW = W_DINV + N;      // 1985
constexpr int META_END = (META_RAW + 3) & ~3;     // 1988

constexpr int XT_LD  = 98;
constexpr int W_XT   = META_END;                  // float[64][98] (x^T, later t2)
constexpr int U0     = W_XT + N * XT_LD;          // 8260

constexpr int W_XAGG  = U0;                       // float[64][98]
constexpr int W1T_LD  = 68;
constexpr int W2T_LD  = 100;
constexpr int WBUF_WORDS = 96 * W1T_LD;           // 6528
constexpr int W_WBUF  = W_XAGG + N * XT_LD;       // 14532
constexpr int H1T_LD  = 68;
constexpr int W_H1T   = W_WBUF + WBUF_WORDS;      // 21060
constexpr int SMEM1_WORDS = W_H1T + N * H1T_LD;   // 25412
constexpr int SMEM1_BYTES = SMEM1_WORDS * 4;      // ~101.6 KB -> 2 CTAs/SM

static_assert((W_XT   % 2) == 0, "xT 8B align");
static_assert((W_WBUF % 4) == 0, "wbuf 16B align");
static_assert((W_H1T  % 4) == 0, "h1t align");

// ---- kernel2 ----
constexpr int BK_LD = 200;                        // bf16 elems per im2col row
constexpr int SMEM2_BYTES = 2 * 96 * BK_LD * 2;   // 76.8 KB -> 2 CTAs/SM
}

// ---- device scratch (static; no allocations) ----
__device__ float         g_h2[(size_t)B * N * S];       // 12.6 MB
__device__ __nv_bfloat16 g_whi[(size_t)H * KC];
__device__ __nv_bfloat16 g_wlo[(size_t)H * KC];

// ---- packed f32x2 helpers ----
__device__ __forceinline__ unsigned long long dup2(float v) {
    unsigned long long r;
    asm("mov.b64 %0, {%1, %1};" : "=l"(r) : "f"(v));
    return r;
}
__device__ __forceinline__ void unpack2(unsigned long long v, float& lo, float& hi) {
    asm("mov.b64 {%0, %1}, %2;" : "=f"(lo), "=f"(hi) : "l"(v));
}
__device__ __forceinline__ void fma2(unsigned long long& d,
                                     unsigned long long a, unsigned long long b) {
    asm("fma.rn.f32x2 %0, %1, %2, %0;" : "+l"(d) : "l"(a), "l"(b));
}

// ---- mma.sync bf16 m16n8k16 ----
__device__ __forceinline__ void mma16816(float* c, const unsigned* a,
                                         unsigned b0, unsigned b1) {
    asm volatile(
        "mma.sync.aligned.m16n8k16.row.col.f32.bf16.bf16.f32 "
        "{%0,%1,%2,%3}, {%4,%5,%6,%7}, {%8,%9}, {%0,%1,%2,%3};"
        : "+f"(c[0]), "+f"(c[1]), "+f"(c[2]), "+f"(c[3])
        : "r"(a[0]), "r"(a[1]), "r"(a[2]), "r"(a[3]), "r"(b0), "r"(b1));
}

// ================= kernel0: split conv_w to bf16 hi/lo =================
__global__ void conv_w_split_kernel(const float* __restrict__ cw) {
    int i = blockIdx.x * blockDim.x + threadIdx.x;
    if (i < H * KC) {
        float v = cw[i];
        __nv_bfloat16 hv = __float2bfloat16(v);
        g_whi[i] = hv;
        g_wlo[i] = __float2bfloat16(v - __bfloat162float(hv));
    }
}

// ================= kernel1: GCN phases 0-4 =================
__global__ __launch_bounds__(NTHREADS, 2)
void gcn_front_kernel(const float* __restrict__ x,
                      const int*   __restrict__ edge_index,
                      const float* __restrict__ W1,
                      const float* __restrict__ b1,
                      const float* __restrict__ W2,
                      const float* __restrict__ b2)
{
    extern __shared__ float sm[];
    int*   s_src  = (int*)(sm + W_SRC);
    int*   s_dst  = (int*)(sm + W_DST);
    int*   s_deg  = (int*)(sm + W_DEG);
    int*   s_off  = (int*)(sm + W_OFFS);
    int*   s_cnt  = (int*)(sm + W_CNT);
    int*   s_eid  = (int*)(sm + W_EID);
    float* s_dinv = sm + W_DINV;
    float* s_xT   = sm + W_XT;    // [64][98]; later t2
    float* s_xagg = sm + W_XAGG;  // [64][98]
    float* s_wbuf = sm + W_WBUF;
    float* s_h1t  = sm + W_H1T;

    const int tid = threadIdx.x;
    const int bid = blockIdx.x;
    const int tx  = tid & 15;
    const int ty  = tid >> 4;

    // ---------- Phase 0: edges, x^T, degrees, CSR ----------
    const int* ei = edge_index + (size_t)bid * 2 * E;
    for (int i = tid; i < E; i += NTHREADS) {
        s_src[i] = ei[i];
        s_dst[i] = ei[E + i];
    }
    if (tid < N) {
        s_src[E + tid] = tid;
        s_dst[E + tid] = tid;
        s_deg[tid] = 0;
        s_cnt[tid] = 0;
    }
    const float* xb = x + (size_t)bid * S * N;
    for (int i = tid; i < S * N; i += NTHREADS) {
        int s = i >> 6, n = i & 63;
        s_xT[n * XT_LD + s] = xb[i];
    }
    __syncthreads();

    for (int i = tid; i < NE; i += NTHREADS) atomicAdd(&s_deg[s_dst[i]], 1);
    __syncthreads();
    if (tid < N) s_dinv[tid] = rsqrtf((float)s_deg[tid]);
    if (tid == 0) {
        int acc = 0;
        for (int n = 0; n < N; n++) { s_off[n] = acc; acc += s_deg[n]; }
        s_off[N] = acc;
    }
    __syncthreads();
    for (int i = tid; i < NE; i += NTHREADS) {
        int d = s_dst[i];
        int pos = s_off[d] + atomicAdd(&s_cnt[d], 1);
        s_eid[pos] = i;
    }
    __syncthreads();

    // ---------- Phase 1: xagg = A_hat * x^T ----------
    for (int p = tid; p < N * S; p += NTHREADS) {
        int n = p & 63, s = p >> 6;
        float acc = 0.f;
        const int e0 = s_off[n], e1 = s_off[n + 1];
        for (int q = e0; q < e1; q++) {
            int sr = s_src[s_eid[q]];
            acc += s_dinv[sr] * s_xT[sr * XT_LD + s];
        }
        s_xagg[n * XT_LD + s] = acc * s_dinv[n];
    }
    __syncthreads();

    // ---------- Phase 2+3 fused (f32x2) ----------
    unsigned long long acc2[4][3];
    #pragma unroll
    for (int i = 0; i < 4; i++)
        #pragma unroll
        for (int j = 0; j < 3; j++) acc2[i][j] = 0ull;

    for (int kt = 0; kt < H; kt += 64) {
        for (int i = tid; i < 64 * S; i += NTHREADS) {
            int hh = i / S, s = i - hh * S;
            s_wbuf[s * W1T_LD + hh] = W1[(size_t)(kt + hh) * S + s];
        }
        __syncthreads();

        unsigned long long acc1[4][2];
        #pragma unroll
        for (int i = 0; i < 4; i++) { acc1[i][0] = 0ull; acc1[i][1] = 0ull; }

        #pragma unroll 4
        for (int s = 0; s < S; s++) {
            unsigned long long ad[4];
            #pragma unroll
            for (int i = 0; i < 4; i++)
                ad[i] = dup2(s_xagg[(ty + 16 * i) * XT_LD + s]);
            const ulonglong2 wv =
                *reinterpret_cast<const ulonglong2*>(&s_wbuf[s * W1T_LD + tx * 4]);
            #pragma unroll
            for (int i = 0; i < 4; i++) {
                fma2(acc1[i][0], ad[i], wv.x);
                fma2(acc1[i][1], ad[i], wv.y);
            }
        }
        #pragma unroll
        for (int jp = 0; jp < 2; jp++) {
            int hc = kt + tx * 4 + 2 * jp;
            float bv0 = b1[hc], bv1 = b1[hc + 1];
            #pragma unroll
            for (int i = 0; i < 4; i++) {
                float v0, v1;
                unpack2(acc1[i][jp], v0, v1);
                v0 = fmaxf(v0 + bv0, 0.f);
                v1 = fmaxf(v1 + bv1, 0.f);
                s_h1t[(ty + 16 * i) * H1T_LD + tx * 4 + 2 * jp]     = v0;
                s_h1t[(ty + 16 * i) * H1T_LD + tx * 4 + 2 * jp + 1] = v1;
            }
        }
        __syncthreads();

        for (int i = tid; i < S * 64; i += NTHREADS) {
            int s = i >> 6, kk = i & 63;
            s_wbuf[kk * W2T_LD + s] = W2[(size_t)s * H + kt + kk];
        }
        __syncthreads();

        #pragma unroll 4
        for (int kk = 0; kk < 64; kk++) {
            unsigned long long ad[4];
            #pragma unroll
            for (int i = 0; i < 4; i++)
                ad[i] = dup2(s_h1t[(ty + 16 * i) * H1T_LD + kk]);
            unsigned long long w0 =
                *reinterpret_cast<const unsigned long long*>(&s_wbuf[kk * W2T_LD + tx * 6]);
            unsigned long long w1 =
                *reinterpret_cast<const unsigned long long*>(&s_wbuf[kk * W2T_LD + tx * 6 + 2]);
            unsigned long long w2 =
                *reinterpret_cast<const unsigned long long*>(&s_wbuf[kk * W2T_LD + tx * 6 + 4]);
            #pragma unroll
            for (int i = 0; i < 4; i++) {
                fma2(acc2[i][0], ad[i], w0);
                fma2(acc2[i][1], ad[i], w1);
                fma2(acc2[i][2], ad[i], w2);
            }
        }
        __syncthreads();
    }
    #pragma unroll
    for (int i = 0; i < 4; i++)
        #pragma unroll
        for (int jp = 0; jp < 3; jp++)
            *reinterpret_cast<unsigned long long*>(
                &s_xT[(ty + 16 * i) * XT_LD + tx * 6 + 2 * jp]) = acc2[i][jp];
    __syncthreads();

    // ---------- Phase 4: aggregate t2 (+b2) -> g_h2[b][n][s] ----------
    float* h2b = g_h2 + (size_t)bid * N * S;
    for (int p = tid; p < N * S; p += NTHREADS) {
        int n = p & 63, s = p >> 6;
        float acc = 0.f;
        const int e0 = s_off[n], e1 = s_off[n + 1];
        for (int q = e0; q < e1; q++) {
            int sr = s_src[s_eid[q]];
            acc += s_dinv[sr] * s_xT[sr * XT_LD + s];
        }
        h2b[n * S + s] = acc * s_dinv[n] + b2[s];
    }
}

// ================= kernel2: conv as 3-pass bf16 mma.sync GEMM =================
__global__ __launch_bounds__(NTHREADS, 2)
void conv_mma_kernel(float* __restrict__ out)
{
    extern __shared__ __nv_bfloat16 smb[];
    __nv_bfloat16* Bhi = smb;                 // [96][BK_LD]
    __nv_bfloat16* Blo = smb + 96 * BK_LD;    // [96][BK_LD]

    const int tid = threadIdx.x;
    const int bid = blockIdx.x;
    const int lane = tid & 31;
    const int wid  = tid >> 5;
    const int gid  = lane >> 2;
    const int tig  = lane & 3;

    // ---- build im2col B (hi/lo): B[s][K] = h2[ic][(s+k-1) mod 96], K = ic*3+k ----
    const float* h2b = g_h2 + (size_t)bid * N * S;
    for (int i = tid; i < 96 * KC; i += NTHREADS) {
        int s = i / KC, K = i - s * KC;
        int ic = K / 3, k = K - ic * 3;
        int t = s + k - 1;
        if (t < 0) t += 96;
        if (t >= 96) t -= 96;
        float v = h2b[ic * S + t];
        __nv_bfloat16 hv = __float2bfloat16(v);
        Bhi[s * BK_LD + K] = hv;
        Blo[s * BK_LD + K] = __float2bfloat16(v - __bfloat162float(hv));
    }
    __syncthreads();

    float* outb = out + (size_t)bid * S * H;
    const int o0 = wid * 64;

    for (int mt = 0; mt < 4; mt++) {
        const int m = o0 + mt * 16;
        float acc[12][4];
        #pragma unroll
        for (int nt = 0; nt < 12; nt++)
            #pragma unroll
            for (int q = 0; q < 4; q++) acc[nt][q] = 0.f;

        const int r0 = (m + gid) * KC;
        const int r1 = (m + gid + 8) * KC;

        for (int kc = 0; kc < 12; kc++) {
            const int c0 = kc * 16 + 2 * tig;
            unsigned ahi[4], alo[4];
            ahi[0] = *(const unsigned*)&g_whi[r0 + c0];
            ahi[1] = *(const unsigned*)&g_whi[r1 + c0];
            ahi[2] = *(const unsigned*)&g_whi[r0 + c0 + 8];
            ahi[3] = *(const unsigned*)&g_whi[r1 + c0 + 8];
            alo[0] = *(const unsigned*)&g_wlo[r0 + c0];
            alo[1] = *(const unsigned*)&g_wlo[r1 + c0];
            alo[2] = *(const unsigned*)&g_wlo[r0 + c0 + 8];
            alo[3] = *(const unsigned*)&g_wlo[r1 + c0 + 8];

            #pragma unroll
            for (int nt = 0; nt < 12; nt++) {
                const int row = nt * 8 + gid;
                unsigned bh0 = *(const unsigned*)&Bhi[row * BK_LD + c0];
                unsigned bh1 = *(const unsigned*)&Bhi[row * BK_LD + c0 + 8];
                unsigned bl0 = *(const unsigned*)&Blo[row * BK_LD + c0];
                unsigned bl1 = *(const unsigned*)&Blo[row * BK_LD + c0 + 8];
                mma16816(acc[nt], ahi, bh0, bh1);
                mma16816(acc[nt], ahi, bl0, bl1);
                mma16816(acc[nt], alo, bh0, bh1);
            }
        }

        // ---- write D[o][s] -> out[b][s][o] ----
        #pragma unroll
        for (int nt = 0; nt < 12; nt++) {
            const int s0 = nt * 8 + 2 * tig;
            const int o  = m + gid;
            outb[(size_t)s0 * H + o]           = acc[nt][0];
            outb[(size_t)(s0 + 1) * H + o]     = acc[nt][1];
            outb[(size_t)s0 * H + o + 8]       = acc[nt][2];
            outb[(size_t)(s0 + 1) * H + o + 8] = acc[nt][3];
        }
    }
}

extern "C" void kernel_launch(void* const* d_in, const int* in_sizes, int n_in,
                              void* d_out, int out_size)
{
    const float* x   = (const float*)d_in[0];
    const int*   ei  = (const int*)  d_in[1];
    const float* W1  = (const float*)d_in[2];
    const float* b1  = (const float*)d_in[3];
    const float* W2  = (const float*)d_in[4];
    const float* b2  = (const float*)d_in[5];
    const float* cw  = (const float*)d_in[6];
    float* out = (float*)d_out;

    conv_w_split_kernel<<<(H * KC + 255) / 256, 256>>>(cw);

    cudaFuncSetAttribute(gcn_front_kernel,
                         cudaFuncAttributeMaxDynamicSharedMemorySize, SMEM1_BYTES);
    gcn_front_kernel<<<B, NTHREADS, SMEM1_BYTES>>>(x, ei, W1, b1, W2, b2);

    cudaFuncSetAttribute(conv_mma_kernel,
                         cudaFuncAttributeMaxDynamicSharedMemorySize, SMEM2_BYTES);
    conv_mma_kernel<<<B, NTHREADS, SMEM2_BYTES>>>(out);
}

// round 13
// speedup vs baseline: 1.9123x; 1.0259x over previous
#include <cuda_runtime.h>
#include <cuda_bf16.h>

namespace {
constexpr int B = 512, S = 96, N = 64, H = 512, E = 512;
constexpr int NE = E + N;
constexpr int NTHREADS = 256;
constexpr int KC = 192;                   // conv im2col K

// ---- kernel1 shared memory layout ----
constexpr int W_SRC  = 0;                 // int[576]
constexpr int W_DST  = W_SRC + NE;        // int[576]
constexpr int W_DEG  = W_DST + NE;        // int[64]
constexpr int W_OFFS = W_DEG + N;         // int[65]
constexpr int W_CNT  = W_OFFS + N + 1;    // int[64]
constexpr int W_EID  = W_CNT + N;         // int[576]
constexpr int W_DINV = W_EID + NE;        // float[64]
constexpr int META_RAW = W_DINV + N;      // 1985
constexpr int META_END = (META_RAW + 3) & ~3;     // 1988

constexpr int XT_LD  = 98;
constexpr int W_XT   = META_END;                  // float[64][98] (x^T, later t2)
constexpr int U0_BYTES = (W_XT + N * XT_LD) * 4;  // 33040, 16B aligned

// bf16 regions (byte offsets)
constexpr int AG_LD   = 104;                      // xagg bf16 row stride (elems)
constexpr int XAGG_HI_B = U0_BYTES;               // [64][104] bf16
constexpr int XAGG_LO_B = XAGG_HI_B + N * AG_LD * 2;   // 46352
constexpr int H1_LD   = 136;                      // h1 tile bf16 row stride (elems)
constexpr int H1_HI_B = XAGG_LO_B + N * AG_LD * 2;     // 59664
constexpr int H1_LO_B = H1_HI_B + N * H1_LD * 2;       // 77072
constexpr int SMEM1_BYTES = H1_LO_B + N * H1_LD * 2;   // 94480 -> 2 CTAs/SM

static_assert((XAGG_HI_B % 16) == 0 && (XAGG_LO_B % 16) == 0, "ag align");
static_assert((H1_HI_B % 16) == 0 && (H1_LO_B % 16) == 0, "h1 align");

// ---- kernel2 ----
constexpr int BK_LD = 200;                        // bf16 elems per im2col row
constexpr int SMEM2_BYTES = 2 * 96 * BK_LD * 2;   // 76.8 KB -> 2 CTAs/SM
}

// ---- device scratch (static; no allocations) ----
__device__ float         g_h2[(size_t)B * N * S];       // 12.6 MB
__device__ __nv_bfloat16 g_whi[(size_t)H * KC];
__device__ __nv_bfloat16 g_wlo[(size_t)H * KC];
__device__ __nv_bfloat16 g_w1hi[(size_t)H * S];         // W1 [512][96]
__device__ __nv_bfloat16 g_w1lo[(size_t)H * S];
__device__ __nv_bfloat16 g_w2hi[(size_t)S * H];         // W2 [96][512]
__device__ __nv_bfloat16 g_w2lo[(size_t)S * H];

// ---- helpers ----
__device__ __forceinline__ unsigned smem_u32_of(const void* p) {
    unsigned a;
    asm("{ .reg .u64 t; cvta.to.shared.u64 t, %1; cvt.u32.u64 %0, t; }"
        : "=r"(a) : "l"(p));
    return a;
}
__device__ __forceinline__ void ldsm_x4(unsigned* r, unsigned saddr) {
    asm volatile("ldmatrix.sync.aligned.m8n8.x4.shared.b16 {%0,%1,%2,%3}, [%4];"
                 : "=r"(r[0]), "=r"(r[1]), "=r"(r[2]), "=r"(r[3]) : "r"(saddr));
}
__device__ __forceinline__ void mma16816(float* c, const unsigned* a,
                                         unsigned b0, unsigned b1) {
    asm volatile(
        "mma.sync.aligned.m16n8k16.row.col.f32.bf16.bf16.f32 "
        "{%0,%1,%2,%3}, {%4,%5,%6,%7}, {%8,%9}, {%0,%1,%2,%3};"
        : "+f"(c[0]), "+f"(c[1]), "+f"(c[2]), "+f"(c[3])
        : "r"(a[0]), "r"(a[1]), "r"(a[2]), "r"(a[3]), "r"(b0), "r"(b1));
}
__device__ __forceinline__ unsigned pack_bf2(__nv_bfloat16 lo, __nv_bfloat16 hi) {
    __nv_bfloat162 p(lo, hi);
    return *reinterpret_cast<unsigned*>(&p);
}

// ================= kernel0: split conv_w, W1, W2 to bf16 hi/lo =================
__global__ void weights_split_kernel(const float* __restrict__ cw,
                                     const float* __restrict__ W1,
                                     const float* __restrict__ W2) {
    int i = blockIdx.x * blockDim.x + threadIdx.x;
    if (i < H * KC) {
        float v = cw[i];
        __nv_bfloat16 hv = __float2bfloat16(v);
        g_whi[i] = hv;
        g_wlo[i] = __float2bfloat16(v - __bfloat162float(hv));
    }
    int j = i - H * KC;
    if (j >= 0 && j < H * S) {
        float v = W1[j];
        __nv_bfloat16 hv = __float2bfloat16(v);
        g_w1hi[j] = hv;
        g_w1lo[j] = __float2bfloat16(v - __bfloat162float(hv));
        float v2 = W2[j];
        __nv_bfloat16 hv2 = __float2bfloat16(v2);
        g_w2hi[j] = hv2;
        g_w2lo[j] = __float2bfloat16(v2 - __bfloat162float(hv2));
    }
}

// ================= kernel1: GCN phases 0-4, GEMMs on tensor pipe =================
__global__ __launch_bounds__(NTHREADS, 2)
void gcn_front_kernel(const float* __restrict__ x,
                      const int*   __restrict__ edge_index,
                      const float* __restrict__ b1,
                      const float* __restrict__ b2)
{
    extern __shared__ float sm[];
    int*   s_src  = (int*)(sm + W_SRC);
    int*   s_dst  = (int*)(sm + W_DST);
    int*   s_deg  = (int*)(sm + W_DEG);
    int*   s_off  = (int*)(sm + W_OFFS);
    int*   s_cnt  = (int*)(sm + W_CNT);
    int*   s_eid  = (int*)(sm + W_EID);
    float* s_dinv = sm + W_DINV;
    float* s_xT   = sm + W_XT;    // [64][98]; x^T, later t2
    char*  smc    = (char*)sm;

    const int tid = threadIdx.x;
    const int bid = blockIdx.x;

    // ---------- Phase 0: edges, x^T, degrees, CSR ----------
    const int* ei = edge_index + (size_t)bid * 2 * E;
    for (int i = tid; i < E; i += NTHREADS) {
        s_src[i] = ei[i];
        s_dst[i] = ei[E + i];
    }
    if (tid < N) {
        s_src[E + tid] = tid;
        s_dst[E + tid] = tid;
        s_deg[tid] = 0;
        s_cnt[tid] = 0;
    }
    const float* xb = x + (size_t)bid * S * N;
    for (int i = tid; i < S * N; i += NTHREADS) {
        int s = i >> 6, n = i & 63;
        s_xT[n * XT_LD + s] = xb[i];
    }
    __syncthreads();

    for (int i = tid; i < NE; i += NTHREADS) atomicAdd(&s_deg[s_dst[i]], 1);
    __syncthreads();
    if (tid < N) s_dinv[tid] = rsqrtf((float)s_deg[tid]);
    if (tid == 0) {
        int acc = 0;
        for (int n = 0; n < N; n++) { s_off[n] = acc; acc += s_deg[n]; }
        s_off[N] = acc;
    }
    __syncthreads();
    for (int i = tid; i < NE; i += NTHREADS) {
        int d = s_dst[i];
        int pos = s_off[d] + atomicAdd(&s_cnt[d], 1);
        s_eid[pos] = i;
    }
    __syncthreads();

    // ---------- Phase 1: xagg = A_hat * x^T -> bf16 hi/lo ----------
    for (int p = tid; p < N * S; p += NTHREADS) {
        int n = p & 63, s = p >> 6;
        float acc = 0.f;
        const int e0 = s_off[n], e1 = s_off[n + 1];
        for (int q = e0; q < e1; q++) {
            int sr = s_src[s_eid[q]];
            acc += s_dinv[sr] * s_xT[sr * XT_LD + s];
        }
        float v = acc * s_dinv[n];
        __nv_bfloat16 hv = __float2bfloat16(v);
        __nv_bfloat16 lv = __float2bfloat16(v - __bfloat162float(hv));
        *(__nv_bfloat16*)(smc + XAGG_HI_B + (n * AG_LD + s) * 2) = hv;
        *(__nv_bfloat16*)(smc + XAGG_LO_B + (n * AG_LD + s) * 2) = lv;
    }
    __syncthreads();

    // ---------- Phases 2+3: mma GEMM1 (relu) + GEMM2, H-tiled ----------
    const int lane = tid & 31;
    const int wid  = tid >> 5;
    const int gid  = lane >> 2;
    const int tig  = lane & 3;
    const int wr   = wid & 3;       // warp row (m)
    const int wc   = wid >> 2;      // warp col (n)
    const int m0   = 16 * wr;

    const unsigned sbase   = smem_u32_of(sm);
    const unsigned ag_hi_s = sbase + XAGG_HI_B;
    const unsigned ag_lo_s = sbase + XAGG_LO_B;
    const unsigned h1_hi_s = sbase + H1_HI_B;
    const unsigned h1_lo_s = sbase + H1_LO_B;
    const unsigned arow16  = (unsigned)(m0 + (lane & 15));
    const unsigned asel16  = (unsigned)((lane >> 4) * 16);

    float t2acc[6][4];
    #pragma unroll
    for (int nt = 0; nt < 6; nt++)
        #pragma unroll
        for (int q = 0; q < 4; q++) t2acc[nt][q] = 0.f;

    for (int ht = 0; ht < 4; ht++) {
        // --- GEMM1 tile: h1[m=64, n=128 cols at ht*128] ---
        float acc1[8][4];
        #pragma unroll
        for (int nt = 0; nt < 8; nt++)
            #pragma unroll
            for (int q = 0; q < 4; q++) acc1[nt][q] = 0.f;

        for (int kk = 0; kk < 6; kk++) {
            unsigned ah[4], al[4];
            unsigned aoff = arow16 * (AG_LD * 2) + kk * 32 + asel16;
            ldsm_x4(ah, ag_hi_s + aoff);
            ldsm_x4(al, ag_lo_s + aoff);
            #pragma unroll
            for (int nt = 0; nt < 8; nt++) {
                int n = ht * 128 + wc * 64 + nt * 8 + gid;
                int bo = n * S + kk * 16 + 2 * tig;
                unsigned bh0 = *(const unsigned*)&g_w1hi[bo];
                unsigned bh1 = *(const unsigned*)&g_w1hi[bo + 8];
                unsigned bl0 = *(const unsigned*)&g_w1lo[bo];
                unsigned bl1 = *(const unsigned*)&g_w1lo[bo + 8];
                mma16816(acc1[nt], ah, bh0, bh1);
                mma16816(acc1[nt], ah, bl0, bl1);
                mma16816(acc1[nt], al, bh0, bh1);
            }
        }
        // bias + relu + bf16 split -> h1 tile smem
        #pragma unroll
        for (int nt = 0; nt < 8; nt++) {
            int hc = ht * 128 + wc * 64 + nt * 8 + 2 * tig;
            int lc = wc * 64 + nt * 8 + 2 * tig;
            float bv0 = b1[hc], bv1 = b1[hc + 1];
            float v0 = fmaxf(acc1[nt][0] + bv0, 0.f);
            float v1 = fmaxf(acc1[nt][1] + bv1, 0.f);
            float v2 = fmaxf(acc1[nt][2] + bv0, 0.f);
            float v3 = fmaxf(acc1[nt][3] + bv1, 0.f);
            __nv_bfloat16 h0 = __float2bfloat16(v0), h1v = __float2bfloat16(v1);
            __nv_bfloat16 h2v = __float2bfloat16(v2), h3 = __float2bfloat16(v3);
            __nv_bfloat16 l0 = __float2bfloat16(v0 - __bfloat162float(h0));
            __nv_bfloat16 l1 = __float2bfloat16(v1 - __bfloat162float(h1v));
            __nv_bfloat16 l2 = __float2bfloat16(v2 - __bfloat162float(h2v));
            __nv_bfloat16 l3 = __float2bfloat16(v3 - __bfloat162float(h3));
            unsigned ra = (m0 + gid) * (H1_LD * 2) + lc * 2;
            unsigned rb = (m0 + gid + 8) * (H1_LD * 2) + lc * 2;
            *(unsigned*)(smc + H1_HI_B + ra) = pack_bf2(h0, h1v);
            *(unsigned*)(smc + H1_LO_B + ra) = pack_bf2(l0, l1);
            *(unsigned*)(smc + H1_HI_B + rb) = pack_bf2(h2v, h3);
            *(unsigned*)(smc + H1_LO_B + rb) = pack_bf2(l2, l3);
        }
        __syncthreads();

        // --- GEMM2 accumulate: t2[m=64, s=96] += h1_tile @ W2_tile^T ---
        for (int kk = 0; kk < 8; kk++) {
            unsigned ah[4], al[4];
            unsigned aoff = arow16 * (H1_LD * 2) + kk * 32 + asel16;
            ldsm_x4(ah, h1_hi_s + aoff);
            ldsm_x4(al, h1_lo_s + aoff);
            #pragma unroll
            for (int nt = 0; nt < 6; nt++) {
                int n = wc * 48 + nt * 8 + gid;          // s index
                int bo = n * H + ht * 128 + kk * 16 + 2 * tig;
                unsigned bh0 = *(const unsigned*)&g_w2hi[bo];
                unsigned bh1 = *(const unsigned*)&g_w2hi[bo + 8];
                unsigned bl0 = *(const unsigned*)&g_w2lo[bo];
                unsigned bl1 = *(const unsigned*)&g_w2lo[bo + 8];
                mma16816(t2acc[nt], ah, bh0, bh1);
                mma16816(t2acc[nt], ah, bl0, bl1);
                mma16816(t2acc[nt], al, bh0, bh1);
            }
        }
        __syncthreads();   // h1 tile reusable next iteration
    }

    // write t2 -> s_xT fp32 [node][s]
    #pragma unroll
    for (int nt = 0; nt < 6; nt++) {
        int n0 = wc * 48 + nt * 8 + 2 * tig;
        s_xT[(m0 + gid) * XT_LD + n0]         = t2acc[nt][0];
        s_xT[(m0 + gid) * XT_LD + n0 + 1]     = t2acc[nt][1];
        s_xT[(m0 + gid + 8) * XT_LD + n0]     = t2acc[nt][2];
        s_xT[(m0 + gid + 8) * XT_LD + n0 + 1] = t2acc[nt][3];
    }
    __syncthreads();

    // ---------- Phase 4: aggregate t2 (+b2) -> g_h2[b][n][s] ----------
    float* h2b = g_h2 + (size_t)bid * N * S;
    for (int p = tid; p < N * S; p += NTHREADS) {
        int n = p & 63, s = p >> 6;
        float acc = 0.f;
        const int e0 = s_off[n], e1 = s_off[n + 1];
        for (int q = e0; q < e1; q++) {
            int sr = s_src[s_eid[q]];
            acc += s_dinv[sr] * s_xT[sr * XT_LD + s];
        }
        h2b[n * S + s] = acc * s_dinv[n] + b2[s];
    }
}

// ================= kernel2: conv as 3-pass bf16 mma.sync GEMM =================
__global__ __launch_bounds__(NTHREADS, 2)
void conv_mma_kernel(float* __restrict__ out)
{
    extern __shared__ __nv_bfloat16 smb[];
    __nv_bfloat16* Bhi = smb;                 // [96][BK_LD]
    __nv_bfloat16* Blo = smb + 96 * BK_LD;    // [96][BK_LD]

    const int tid = threadIdx.x;
    const int bid = blockIdx.x;
    const int lane = tid & 31;
    const int wid  = tid >> 5;
    const int gid  = lane >> 2;
    const int tig  = lane & 3;

    // ---- build im2col B (hi/lo): B[s][K] = h2[ic][(s+k-1) mod 96], K = ic*3+k ----
    const float* h2b = g_h2 + (size_t)bid * N * S;
    for (int i = tid; i < 96 * KC; i += NTHREADS) {
        int s = i / KC, K = i - s * KC;
        int ic = K / 3, k = K - ic * 3;
        int t = s + k - 1;
        if (t < 0) t += 96;
        if (t >= 96) t -= 96;
        float v = h2b[ic * S + t];
        __nv_bfloat16 hv = __float2bfloat16(v);
        Bhi[s * BK_LD + K] = hv;
        Blo[s * BK_LD + K] = __float2bfloat16(v - __bfloat162float(hv));
    }
    __syncthreads();

    float* outb = out + (size_t)bid * S * H;
    const int o0 = wid * 64;

    for (int mt = 0; mt < 4; mt++) {
        const int m = o0 + mt * 16;
        float acc[12][4];
        #pragma unroll
        for (int nt = 0; nt < 12; nt++)
            #pragma unroll
            for (int q = 0; q < 4; q++) acc[nt][q] = 0.f;

        const int r0 = (m + gid) * KC;
        const int r1 = (m + gid + 8) * KC;

        for (int kc = 0; kc < 12; kc++) {
            const int c0 = kc * 16 + 2 * tig;
            unsigned ahi[4], alo[4];
            ahi[0] = *(const unsigned*)&g_whi[r0 + c0];
            ahi[1] = *(const unsigned*)&g_whi[r1 + c0];
            ahi[2] = *(const unsigned*)&g_whi[r0 + c0 + 8];
            ahi[3] = *(const unsigned*)&g_whi[r1 + c0 + 8];
            alo[0] = *(const unsigned*)&g_wlo[r0 + c0];
            alo[1] = *(const unsigned*)&g_wlo[r1 + c0];
            alo[2] = *(const unsigned*)&g_wlo[r0 + c0 + 8];
            alo[3] = *(const unsigned*)&g_wlo[r1 + c0 + 8];

            #pragma unroll
            for (int nt = 0; nt < 12; nt++) {
                const int row = nt * 8 + gid;
                unsigned bh0 = *(const unsigned*)&Bhi[row * BK_LD + c0];
                unsigned bh1 = *(const unsigned*)&Bhi[row * BK_LD + c0 + 8];
                unsigned bl0 = *(const unsigned*)&Blo[row * BK_LD + c0];
                unsigned bl1 = *(const unsigned*)&Blo[row * BK_LD + c0 + 8];
                mma16816(acc[nt], ahi, bh0, bh1);
                mma16816(acc[nt], ahi, bl0, bl1);
                mma16816(acc[nt], alo, bh0, bh1);
            }
        }

        // ---- write D[o][s] -> out[b][s][o] ----
        #pragma unroll
        for (int nt = 0; nt < 12; nt++) {
            const int s0 = nt * 8 + 2 * tig;
            const int o  = m + gid;
            outb[(size_t)s0 * H + o]           = acc[nt][0];
            outb[(size_t)(s0 + 1) * H + o]     = acc[nt][1];
            outb[(size_t)s0 * H + o + 8]       = acc[nt][2];
            outb[(size_t)(s0 + 1) * H + o + 8] = acc[nt][3];
        }
    }
}

extern "C" void kernel_launch(void* const* d_in, const int* in_sizes, int n_in,
                              void* d_out, int out_size)
{
    const float* x   = (const float*)d_in[0];
    const int*   ei  = (const int*)  d_in[1];
    const float* W1  = (const float*)d_in[2];
    const float* b1  = (const float*)d_in[3];
    const float* W2  = (const float*)d_in[4];
    const float* b2  = (const float*)d_in[5];
    const float* cw  = (const float*)d_in[6];
    float* out = (float*)d_out;

    weights_split_kernel<<<(H * KC + H * S + 255) / 256, 256>>>(cw, W1, W2);

    cudaFuncSetAttribute(gcn_front_kernel,
                         cudaFuncAttributeMaxDynamicSharedMemorySize, SMEM1_BYTES);
    gcn_front_kernel<<<B, NTHREADS, SMEM1_BYTES>>>(x, ei, b1, b2);

    cudaFuncSetAttribute(conv_mma_kernel,
                         cudaFuncAttributeMaxDynamicSharedMemorySize, SMEM2_BYTES);
    conv_mma_kernel<<<B, NTHREADS, SMEM2_BYTES>>>(out);
}